// round 3
// baseline (speedup 1.0000x reference)
#include <cuda_runtime.h>
#include <cstdint>
#include <math.h>

// Problem constants (fixed by reference setup_inputs)
#define B_    8
#define N_    2048
#define D_    512
#define H_    1024
#define E_    8
#define CAP_  512
#define BN_   (B_*N_)          // 16384 tokens
#define EB_   (E_*B_)          // 64 expert-batch pairs
#define SLOTS_ (EB_*CAP_)      // 32768 slots
#define OUT_MAIN_ ((size_t)B_*N_*D_)   // 8388608

// ---------------- scratch (no cudaMalloc allowed) ----------------
__device__ float g_raw[BN_*E_];        // softmax probs per token (for aux loss)
__device__ int   g_idx1[BN_];
__device__ int   g_idx2[BN_];
__device__ float g_g1[BN_];            // normalized gate1
__device__ float g_g2[BN_];            // normalized gate2
__device__ int   g_keep2[BN_];         // random-policy keep flag for 2nd expert
__device__ int   g_slot_tok[SLOTS_];   // global token id per (e,b,c) slot, -1 empty
__device__ float g_slot_gate[SLOTS_];  // gate for that slot
__device__ float g_hid[(size_t)EB_*CAP_*H_];  // 128 MiB intermediate
__device__ float g_lossp[B_];

// ---------------- packed f32x2 helpers (Blackwell FFMA2 path) ----------------
__device__ __forceinline__ unsigned long long pk2(float x, float y) {
    unsigned long long r;
    asm("mov.b64 %0, {%1, %2};" : "=l"(r) : "f"(x), "f"(y));
    return r;
}
__device__ __forceinline__ unsigned long long fma2(unsigned long long a,
                                                   unsigned long long b,
                                                   unsigned long long c) {
    unsigned long long d;
    asm("fma.rn.f32x2 %0, %1, %2, %3;" : "=l"(d) : "l"(a), "l"(b), "l"(c));
    return d;
}
__device__ __forceinline__ float2 up2(unsigned long long v) {
    float2 f;
    asm("mov.b64 {%0, %1}, %2;" : "=f"(f.x), "=f"(f.y) : "l"(v));
    return f;
}
__device__ __forceinline__ float lrelu(float v) { return v >= 0.f ? v : 0.01f * v; }

// ---------------- kernel 1: init ----------------
__global__ void k_init(float* __restrict__ out, int out_n) {
    int i = blockIdx.x * blockDim.x + threadIdx.x;
    int stride = gridDim.x * blockDim.x;
    for (int j = i; j < out_n; j += stride) out[j] = 0.f;
    for (int j = i; j < SLOTS_; j += stride) g_slot_tok[j] = -1;
}

// ---------------- kernel 2: gating (warp per token) ----------------
__global__ void k_gate(const float* __restrict__ x,
                       const float* __restrict__ probs,
                       const float* __restrict__ wg) {
    int lane = threadIdx.x & 31;
    int t = blockIdx.x * (blockDim.x >> 5) + (threadIdx.x >> 5);
    if (t >= BN_) return;
    const float* xr = x + (size_t)t * D_;

    float acc[E_];
#pragma unroll
    for (int e = 0; e < E_; e++) acc[e] = 0.f;

    for (int k = lane; k < D_; k += 32) {
        float xv = xr[k];
        const float4* wr = (const float4*)(wg + k * E_);
        float4 w0 = wr[0], w1v = wr[1];
        acc[0] = fmaf(xv, w0.x, acc[0]);
        acc[1] = fmaf(xv, w0.y, acc[1]);
        acc[2] = fmaf(xv, w0.z, acc[2]);
        acc[3] = fmaf(xv, w0.w, acc[3]);
        acc[4] = fmaf(xv, w1v.x, acc[4]);
        acc[5] = fmaf(xv, w1v.y, acc[5]);
        acc[6] = fmaf(xv, w1v.z, acc[6]);
        acc[7] = fmaf(xv, w1v.w, acc[7]);
    }
#pragma unroll
    for (int off = 16; off; off >>= 1)
#pragma unroll
        for (int e = 0; e < E_; e++)
            acc[e] += __shfl_xor_sync(0xffffffffu, acc[e], off);

    if (lane == 0) {
        // softmax
        float m = acc[0];
#pragma unroll
        for (int e = 1; e < E_; e++) m = fmaxf(m, acc[e]);
        float r[E_], s = 0.f;
#pragma unroll
        for (int e = 0; e < E_; e++) { r[e] = expf(acc[e] - m); s += r[e]; }
        float inv = 1.f / s;
#pragma unroll
        for (int e = 0; e < E_; e++) r[e] *= inv;

        // top-1 (first occurrence on tie, matches jnp.argmax)
        int i1 = 0; float g1 = r[0];
#pragma unroll
        for (int e = 1; e < E_; e++) if (r[e] > g1) { g1 = r[e]; i1 = e; }
        // top-2 excluding i1
        int i2 = -1; float g2 = -1.f;
#pragma unroll
        for (int e = 0; e < E_; e++) if (e != i1 && r[e] > g2) { g2 = r[e]; i2 = e; }

        float denom = g1 + g2 + 1e-9f;
        float g1n = g1 / denom, g2n = g2 / denom;
        int keep2 = probs[t] < (g2n / 0.2f);

        g_idx1[t] = i1; g_idx2[t] = i2;
        g_g1[t] = g1n;  g_g2[t] = g2n;
        g_keep2[t] = keep2;
        float4* rr = (float4*)(g_raw + (size_t)t * E_);
        rr[0] = make_float4(r[0], r[1], r[2], r[3]);
        rr[1] = make_float4(r[4], r[5], r[6], r[7]);
    }
}

// ---------------- kernel 3: capacity scan (one warp per batch) ----------------
__global__ void k_scan() {
    int b = blockIdx.x;
    int lane = threadIdx.x;
    __shared__ int cnt[E_], m1c[E_];
    if (lane < E_) cnt[lane] = 0;
    __syncwarp();

    float sr[E_]; int c1[E_];
#pragma unroll
    for (int e = 0; e < E_; e++) { sr[e] = 0.f; c1[e] = 0; }

    // pass 1: first-choice positions (exclusive cumsum in token order)
    for (int base = 0; base < N_; base += 32) {
        int t = b * N_ + base + lane;
        int e1 = g_idx1[t];
#pragma unroll
        for (int e = 0; e < E_; e++) {
            sr[e] += g_raw[(size_t)t * E_ + e];
            c1[e] += (e1 == e) ? 1 : 0;
        }
        unsigned mm = __match_any_sync(0xffffffffu, e1);
        int rank = __popc(mm & ((1u << lane) - 1u));
        int bc = cnt[e1];
        __syncwarp();
        int pos = bc + rank;
        if (pos < CAP_) {
            int slot = (e1 * B_ + b) * CAP_ + pos;
            g_slot_tok[slot] = t;
            g_slot_gate[slot] = g_g1[t];
        }
        if (rank == 0) cnt[e1] = bc + __popc(mm);
        __syncwarp();
    }

    if (lane < E_) { m1c[lane] = min(cnt[lane], CAP_); cnt[lane] = 0; }
    __syncwarp();

    // pass 2: second-choice (after random-keep threshold), offset by m1_count
    for (int base = 0; base < N_; base += 32) {
        int t = b * N_ + base + lane;
        int alive = g_keep2[t];
        int e2 = g_idx2[t];
        int key = alive ? e2 : (E_ + lane);   // dead lanes get unique keys
        unsigned mm = __match_any_sync(0xffffffffu, key);
        int rank = __popc(mm & ((1u << lane) - 1u));
        int bc = cnt[e2];
        int m1 = m1c[e2];
        __syncwarp();
        if (alive) {
            int pos = m1 + bc + rank;
            if (pos < CAP_) {
                int slot = (e2 * B_ + b) * CAP_ + pos;
                g_slot_tok[slot] = t;
                g_slot_gate[slot] = g_g2[t];
            }
            if (rank == 0) cnt[e2] = bc + __popc(mm);
        }
        __syncwarp();
    }

    // aux-loss partial: sum_e S_raw[e] * C1[e]
#pragma unroll
    for (int e = 0; e < E_; e++) {
#pragma unroll
        for (int off = 16; off; off >>= 1) {
            sr[e] += __shfl_xor_sync(0xffffffffu, sr[e], off);
            c1[e] += __shfl_xor_sync(0xffffffffu, c1[e], off);
        }
    }
    if (lane == 0) {
        float lb = 0.f;
#pragma unroll
        for (int e = 0; e < E_; e++) lb += sr[e] * (float)c1[e];
        g_lossp[b] = lb;
    }
}

// ---------------- kernel 4: GEMM1 (gathered A @ w1, LeakyReLU) ----------------
// C[cap, H] per (e,b); block tile 128x128, BK=8, thread 8x8 via f32x2.
__global__ __launch_bounds__(256, 2) void k_gemm1(const float* __restrict__ x,
                                                  const float* __restrict__ w1) {
    const int eb = blockIdx.z;
    const int e  = eb >> 3;
    const int m0 = blockIdx.y * 128, n0 = blockIdx.x * 128;
    __shared__ float As[8 * 132];
    __shared__ float Bs[8 * 128];

    const int tid  = threadIdx.x;
    const int arow = tid >> 1;
    const int acs  = (tid & 1) * 4;
    const int tok  = g_slot_tok[eb * CAP_ + m0 + arow];
    const float* ap = (tok >= 0) ? (x + (size_t)tok * D_ + acs) : nullptr;

    const int bkr = tid >> 5;
    const int bc  = (tid & 31) * 4;
    const float* bp = w1 + (size_t)e * D_ * H_ + (size_t)bkr * H_ + n0 + bc;

    const int tx = tid & 15, ty = tid >> 4;
    unsigned long long acc[8][4];
#pragma unroll
    for (int i = 0; i < 8; i++)
#pragma unroll
        for (int p = 0; p < 4; p++) acc[i][p] = 0ull;

    for (int k0 = 0; k0 < D_; k0 += 8) {
        float4 av = ap ? *(const float4*)(ap + k0) : make_float4(0.f, 0.f, 0.f, 0.f);
        float4 bv = *(const float4*)(bp + (size_t)k0 * H_);
        __syncthreads();
        As[(acs + 0) * 132 + arow] = av.x;
        As[(acs + 1) * 132 + arow] = av.y;
        As[(acs + 2) * 132 + arow] = av.z;
        As[(acs + 3) * 132 + arow] = av.w;
        *(float4*)&Bs[bkr * 128 + bc] = bv;
        __syncthreads();
#pragma unroll
        for (int kk = 0; kk < 8; kk++) {
            const float* asr = &As[kk * 132];
            float4 a0 = *(const float4*)(asr + ty * 4);
            float4 a1 = *(const float4*)(asr + 64 + ty * 4);
            const float* bsr = &Bs[kk * 128];
            float4 b0 = *(const float4*)(bsr + tx * 4);
            float4 b1 = *(const float4*)(bsr + 64 + tx * 4);
            unsigned long long bpk[4] = { pk2(b0.x, b0.y), pk2(b0.z, b0.w),
                                          pk2(b1.x, b1.y), pk2(b1.z, b1.w) };
            float aarr[8] = {a0.x, a0.y, a0.z, a0.w, a1.x, a1.y, a1.z, a1.w};
#pragma unroll
            for (int i = 0; i < 8; i++) {
                unsigned long long ad = pk2(aarr[i], aarr[i]);
#pragma unroll
                for (int p = 0; p < 4; p++) acc[i][p] = fma2(ad, bpk[p], acc[i][p]);
            }
        }
    }

    float* hb = g_hid + (size_t)(eb * CAP_ + m0) * H_;
#pragma unroll
    for (int i = 0; i < 8; i++) {
        int r = (i < 4) ? (ty * 4 + i) : (60 + ty * 4 + i);
        float2 v0 = up2(acc[i][0]), v1 = up2(acc[i][1]);
        float2 v2 = up2(acc[i][2]), v3 = up2(acc[i][3]);
        float4 s0 = make_float4(lrelu(v0.x), lrelu(v0.y), lrelu(v1.x), lrelu(v1.y));
        float4 s1 = make_float4(lrelu(v2.x), lrelu(v2.y), lrelu(v3.x), lrelu(v3.y));
        *(float4*)&hb[(size_t)r * H_ + n0 + tx * 4]       = s0;
        *(float4*)&hb[(size_t)r * H_ + n0 + 64 + tx * 4]  = s1;
    }
}

// ---------------- kernel 5: GEMM2 (hid @ w2) + fused gated scatter ----------------
__global__ __launch_bounds__(256, 2) void k_gemm2(const float* __restrict__ w2,
                                                  float* __restrict__ out) {
    const int eb = blockIdx.z;
    const int e  = eb >> 3;
    const int m0 = blockIdx.y * 128, n0 = blockIdx.x * 128;
    __shared__ float As[8 * 132];
    __shared__ float Bs[8 * 128];

    const int tid  = threadIdx.x;
    const int arow = tid >> 1;
    const int acs  = (tid & 1) * 4;
    const float* ap = g_hid + (size_t)(eb * CAP_ + m0 + arow) * H_ + acs;

    const int bkr = tid >> 5;
    const int bc  = (tid & 31) * 4;
    const float* bp = w2 + (size_t)e * H_ * D_ + (size_t)bkr * D_ + n0 + bc;

    const int tx = tid & 15, ty = tid >> 4;
    unsigned long long acc[8][4];
#pragma unroll
    for (int i = 0; i < 8; i++)
#pragma unroll
        for (int p = 0; p < 4; p++) acc[i][p] = 0ull;

    for (int k0 = 0; k0 < H_; k0 += 8) {
        float4 av = *(const float4*)(ap + k0);
        float4 bv = *(const float4*)(bp + (size_t)k0 * D_);
        __syncthreads();
        As[(acs + 0) * 132 + arow] = av.x;
        As[(acs + 1) * 132 + arow] = av.y;
        As[(acs + 2) * 132 + arow] = av.z;
        As[(acs + 3) * 132 + arow] = av.w;
        *(float4*)&Bs[bkr * 128 + bc] = bv;
        __syncthreads();
#pragma unroll
        for (int kk = 0; kk < 8; kk++) {
            const float* asr = &As[kk * 132];
            float4 a0 = *(const float4*)(asr + ty * 4);
            float4 a1 = *(const float4*)(asr + 64 + ty * 4);
            const float* bsr = &Bs[kk * 128];
            float4 b0 = *(const float4*)(bsr + tx * 4);
            float4 b1 = *(const float4*)(bsr + 64 + tx * 4);
            unsigned long long bpk[4] = { pk2(b0.x, b0.y), pk2(b0.z, b0.w),
                                          pk2(b1.x, b1.y), pk2(b1.z, b1.w) };
            float aarr[8] = {a0.x, a0.y, a0.z, a0.w, a1.x, a1.y, a1.z, a1.w};
#pragma unroll
            for (int i = 0; i < 8; i++) {
                unsigned long long ad = pk2(aarr[i], aarr[i]);
#pragma unroll
                for (int p = 0; p < 4; p++) acc[i][p] = fma2(ad, bpk[p], acc[i][p]);
            }
        }
    }

    // epilogue: out[tok, :] += gate * eo_row  (<=2 commutative adds per element)
#pragma unroll
    for (int i = 0; i < 8; i++) {
        int r = (i < 4) ? (ty * 4 + i) : (60 + ty * 4 + i);
        int slot = eb * CAP_ + m0 + r;
        int tok  = g_slot_tok[slot];
        if (tok < 0) continue;
        float gate = g_slot_gate[slot];
        float* ob = out + (size_t)tok * D_ + n0;
        float2 v0 = up2(acc[i][0]), v1 = up2(acc[i][1]);
        float2 v2 = up2(acc[i][2]), v3 = up2(acc[i][3]);
        int c0 = tx * 4, c1c = 64 + tx * 4;
        atomicAdd(ob + c0 + 0, gate * v0.x);
        atomicAdd(ob + c0 + 1, gate * v0.y);
        atomicAdd(ob + c0 + 2, gate * v1.x);
        atomicAdd(ob + c0 + 3, gate * v1.y);
        atomicAdd(ob + c1c + 0, gate * v2.x);
        atomicAdd(ob + c1c + 1, gate * v2.y);
        atomicAdd(ob + c1c + 2, gate * v3.x);
        atomicAdd(ob + c1c + 3, gate * v3.y);
    }
}

// ---------------- kernel 6: loss ----------------
__global__ void k_loss(float* __restrict__ out, int out_n) {
    if ((size_t)out_n > OUT_MAIN_) {
        float s = 0.f;
#pragma unroll
        for (int b = 0; b < B_; b++) s += g_lossp[b];
        // loss = LOSS_COEF * sum_{b,e} (S_raw * C1) / n^2   (e^2 / (b*e) * b-sum folds to 1/n^2 * sum)
        out[OUT_MAIN_] = 0.01f * s / ((float)N_ * (float)N_);
    }
}

// ---------------- entry ----------------
extern "C" void kernel_launch(void* const* d_in, const int* in_sizes, int n_in,
                              void* d_out, int out_size) {
    const float* x     = (const float*)d_in[0];
    const float* probs = (const float*)d_in[1];
    const float* wg    = (const float*)d_in[2];
    const float* w1    = (const float*)d_in[3];
    const float* w2    = (const float*)d_in[4];
    float* out = (float*)d_out;

    k_init<<<4096, 256>>>(out, out_size);
    k_gate<<<BN_ / 4, 128>>>(x, probs, wg);
    k_scan<<<B_, 32>>>();
    k_gemm1<<<dim3(H_ / 128, CAP_ / 128, EB_), 256>>>(x, w1);
    k_gemm2<<<dim3(D_ / 128, CAP_ / 128, EB_), 256>>>(w2, out);
    k_loss<<<1, 1>>>(out, out_size);
}

// round 8
// speedup vs baseline: 1.6730x; 1.6730x over previous
#include <cuda_runtime.h>
#include <cuda_bf16.h>
#include <cstdint>
#include <math.h>

// ---------------- problem constants ----------------
#define B_    8
#define N_    2048
#define D_    512
#define H_    1024
#define E_    8
#define CAP_  512
#define BN_   (B_*N_)
#define EB_   (E_*B_)
#define SLOTS_ (EB_*CAP_)
#define OUT_MAIN_ ((size_t)B_*N_*D_)

// GEMM tiling: CTA 128x128, k-chunk 16, 3-stage cp.async pipeline
#define TM 128
#define TN 128
#define TKC 16
#define STAGE 16384            // Ahi 4K + Alo 4K + Bhi 4K + Blo 4K
#define NSTAGE 3               // 48 KB static shared

// ---------------- scratch ----------------
__device__ float g_raw[BN_*E_];
__device__ int   g_idx1[BN_];
__device__ int   g_idx2[BN_];
__device__ float g_g1[BN_];
__device__ float g_g2[BN_];
__device__ int   g_keep2[BN_];
__device__ int   g_slot_tok[SLOTS_];
__device__ int   g_tslot1[BN_];
__device__ int   g_tslot2[BN_];
__device__ float g_lossp[B_];
__device__ __align__(16) __nv_bfloat16 g_x_hi[(size_t)BN_*D_];
__device__ __align__(16) __nv_bfloat16 g_x_lo[(size_t)BN_*D_];
__device__ __align__(16) __nv_bfloat16 g_w1_hi[(size_t)E_*D_*H_];
__device__ __align__(16) __nv_bfloat16 g_w1_lo[(size_t)E_*D_*H_];
__device__ __align__(16) __nv_bfloat16 g_w2_hi[(size_t)E_*H_*D_];
__device__ __align__(16) __nv_bfloat16 g_w2_lo[(size_t)E_*H_*D_];
__device__ __align__(16) __nv_bfloat16 g_hid_hi[(size_t)EB_*CAP_*H_];
__device__ __align__(16) __nv_bfloat16 g_hid_lo[(size_t)EB_*CAP_*H_];
__device__ __align__(16) float         g_eo[(size_t)EB_*CAP_*D_];

// ---------------- PTX helpers (compute_100-safe; no pointer params) ----------------
__device__ __forceinline__ uint32_t smem_u32(const void* p) {
    uint32_t a;
    asm("{ .reg .u64 t; cvta.to.shared.u64 t, %1; cvt.u32.u64 %0, t; }"
        : "=r"(a) : "l"(p));
    return a;
}
#define CP16(dst, src, sz) \
    asm volatile("cp.async.cg.shared.global [%0], [%1], 16, %2;" \
                 :: "r"(dst), "l"(src), "r"(sz) : "memory")
#define CP_COMMIT() asm volatile("cp.async.commit_group;" ::: "memory")
#define CP_WAIT1()  asm volatile("cp.async.wait_group 1;" ::: "memory")

#define LDSM4(R0, R1, R2, R3, ADDR) \
    asm volatile("ldmatrix.sync.aligned.m8n8.x4.shared.b16 {%0,%1,%2,%3}, [%4];" \
        : "=r"(R0), "=r"(R1), "=r"(R2), "=r"(R3) : "r"(ADDR))
#define LDSM4T(R0, R1, R2, R3, ADDR) \
    asm volatile("ldmatrix.sync.aligned.m8n8.x4.trans.shared.b16 {%0,%1,%2,%3}, [%4];" \
        : "=r"(R0), "=r"(R1), "=r"(R2), "=r"(R3) : "r"(ADDR))
#define MMA4(C, A0, A1, A2, A3, B0, B1) \
    asm volatile("mma.sync.aligned.m16n8k16.row.col.f32.bf16.bf16.f32 " \
        "{%0,%1,%2,%3}, {%4,%5,%6,%7}, {%8,%9}, {%0,%1,%2,%3};" \
        : "+f"(C.x), "+f"(C.y), "+f"(C.z), "+f"(C.w) \
        : "r"(A0), "r"(A1), "r"(A2), "r"(A3), "r"(B0), "r"(B1))

__device__ __forceinline__ float lrelu(float v) { return v >= 0.f ? v : 0.01f * v; }
__device__ __forceinline__ void splitf(float v, __nv_bfloat16& h, __nv_bfloat16& l) {
    h = __float2bfloat16(v);
    l = __float2bfloat16(v - __bfloat162float(h));
}
__device__ __forceinline__ uint32_t packb2(__nv_bfloat16 a, __nv_bfloat16 b) {
    return (uint32_t)__bfloat16_as_ushort(a) | ((uint32_t)__bfloat16_as_ushort(b) << 16);
}
__device__ __forceinline__ void split4(float4 v, uint2& uh, uint2& ul) {
    __nv_bfloat16 h0, h1, h2, h3, l0, l1, l2, l3;
    splitf(v.x, h0, l0); splitf(v.y, h1, l1);
    splitf(v.z, h2, l2); splitf(v.w, h3, l3);
    uh = make_uint2(packb2(h0, h1), packb2(h2, h3));
    ul = make_uint2(packb2(l0, l1), packb2(l2, l3));
}

// ---------------- kernel: init ----------------
__global__ void k_init() {
    int i = blockIdx.x * blockDim.x + threadIdx.x;
    if (i < SLOTS_) g_slot_tok[i] = -1;
}

// ---------------- split kernels: reference __device__ globals DIRECTLY ----------------
// (passing __device__ symbols as kernel args from host code gives the HOST shadow
//  address — on GB300/ATS that silently writes host memory; root cause of R5-R7.)
__global__ void k_split_x(const float* __restrict__ src) {
    int i = blockIdx.x * blockDim.x + threadIdx.x;
    if (i >= BN_ * D_ / 4) return;
    uint2 uh, ul;
    split4(((const float4*)src)[i], uh, ul);
    ((uint2*)g_x_hi)[i] = uh;
    ((uint2*)g_x_lo)[i] = ul;
}
__global__ void k_split_w1(const float* __restrict__ src) {
    int i = blockIdx.x * blockDim.x + threadIdx.x;
    if (i >= E_ * D_ * H_ / 4) return;
    uint2 uh, ul;
    split4(((const float4*)src)[i], uh, ul);
    ((uint2*)g_w1_hi)[i] = uh;
    ((uint2*)g_w1_lo)[i] = ul;
}
__global__ void k_split_w2(const float* __restrict__ src) {
    int i = blockIdx.x * blockDim.x + threadIdx.x;
    if (i >= E_ * H_ * D_ / 4) return;
    uint2 uh, ul;
    split4(((const float4*)src)[i], uh, ul);
    ((uint2*)g_w2_hi)[i] = uh;
    ((uint2*)g_w2_lo)[i] = ul;
}

// ---------------- kernel: gating (warp per token) ----------------
__global__ void k_gate(const float* __restrict__ x,
                       const float* __restrict__ probs,
                       const float* __restrict__ wg) {
    int lane = threadIdx.x & 31;
    int t = blockIdx.x * (blockDim.x >> 5) + (threadIdx.x >> 5);
    if (t >= BN_) return;
    const float* xr = x + (size_t)t * D_;
    float acc[E_];
#pragma unroll
    for (int e = 0; e < E_; e++) acc[e] = 0.f;
    for (int k = lane; k < D_; k += 32) {
        float xv = xr[k];
        const float4* wr = (const float4*)(wg + k * E_);
        float4 w0 = wr[0], w1v = wr[1];
        acc[0] = fmaf(xv, w0.x, acc[0]);  acc[1] = fmaf(xv, w0.y, acc[1]);
        acc[2] = fmaf(xv, w0.z, acc[2]);  acc[3] = fmaf(xv, w0.w, acc[3]);
        acc[4] = fmaf(xv, w1v.x, acc[4]); acc[5] = fmaf(xv, w1v.y, acc[5]);
        acc[6] = fmaf(xv, w1v.z, acc[6]); acc[7] = fmaf(xv, w1v.w, acc[7]);
    }
#pragma unroll
    for (int off = 16; off; off >>= 1)
#pragma unroll
        for (int e = 0; e < E_; e++)
            acc[e] += __shfl_xor_sync(0xffffffffu, acc[e], off);
    if (lane == 0) {
        float m = acc[0];
#pragma unroll
        for (int e = 1; e < E_; e++) m = fmaxf(m, acc[e]);
        float r[E_], s = 0.f;
#pragma unroll
        for (int e = 0; e < E_; e++) { r[e] = expf(acc[e] - m); s += r[e]; }
        float inv = 1.f / s;
#pragma unroll
        for (int e = 0; e < E_; e++) r[e] *= inv;
        int i1 = 0; float g1 = r[0];
#pragma unroll
        for (int e = 1; e < E_; e++) if (r[e] > g1) { g1 = r[e]; i1 = e; }
        int i2 = -1; float g2 = -1.f;
#pragma unroll
        for (int e = 0; e < E_; e++) if (e != i1 && r[e] > g2) { g2 = r[e]; i2 = e; }
        float denom = g1 + g2 + 1e-9f;
        float g1n = g1 / denom, g2n = g2 / denom;
        g_idx1[t] = i1; g_idx2[t] = i2;
        g_g1[t] = g1n;  g_g2[t] = g2n;
        g_keep2[t] = probs[t] < (g2n / 0.2f);
        float4* rr = (float4*)(g_raw + (size_t)t * E_);
        rr[0] = make_float4(r[0], r[1], r[2], r[3]);
        rr[1] = make_float4(r[4], r[5], r[6], r[7]);
    }
}

// ---------------- kernel: capacity scan (one warp per batch) ----------------
__global__ void k_scan() {
    int b = blockIdx.x;
    int lane = threadIdx.x;
    __shared__ int cnt[E_], m1c[E_];
    if (lane < E_) cnt[lane] = 0;
    __syncwarp();
    unsigned lmask = (1u << lane) - 1u;

    int e1 = g_idx1[b * N_ + lane];
    for (int base = 0; base < N_; base += 32) {
        int e1n = 0;
        if (base + 32 < N_) e1n = g_idx1[b * N_ + base + 32 + lane];
        int tcur = b * N_ + base + lane;
        unsigned mm = __match_any_sync(0xffffffffu, e1);
        int rank = __popc(mm & lmask);
        int bc = cnt[e1];
        __syncwarp();
        int pos = bc + rank;
        int slot = -1;
        if (pos < CAP_) {
            slot = (e1 * B_ + b) * CAP_ + pos;
            g_slot_tok[slot] = tcur;
        }
        g_tslot1[tcur] = slot;
        if (rank == 0) cnt[e1] = bc + __popc(mm);
        __syncwarp();
        e1 = e1n;
    }
    if (lane < E_) { m1c[lane] = min(cnt[lane], CAP_); cnt[lane] = 0; }
    __syncwarp();

    int alive = g_keep2[b * N_ + lane];
    int e2 = g_idx2[b * N_ + lane];
    for (int base = 0; base < N_; base += 32) {
        int alin = 0, e2n = 0;
        if (base + 32 < N_) {
            int tn = b * N_ + base + 32 + lane;
            alin = g_keep2[tn]; e2n = g_idx2[tn];
        }
        int tcur = b * N_ + base + lane;
        int key = alive ? e2 : (E_ + lane);
        unsigned mm = __match_any_sync(0xffffffffu, key);
        int rank = __popc(mm & lmask);
        int bc = cnt[e2];
        int m1 = m1c[e2];
        __syncwarp();
        int slot = -1;
        if (alive) {
            int pos = m1 + bc + rank;
            if (pos < CAP_) {
                slot = (e2 * B_ + b) * CAP_ + pos;
                g_slot_tok[slot] = tcur;
            }
            if (rank == 0) cnt[e2] = bc + __popc(mm);
        }
        g_tslot2[tcur] = slot;
        __syncwarp();
        alive = alin; e2 = e2n;
    }
}

// ---------------- kernel: aux-loss partials (block per batch) ----------------
__global__ void k_lsum() {
    int b = blockIdx.x, tid = threadIdx.x;
    __shared__ float ssr[E_];
    __shared__ int   sc1[E_];
    if (tid < E_) { ssr[tid] = 0.f; sc1[tid] = 0; }
    __syncthreads();
    float lr[E_]; int lc[E_];
#pragma unroll
    for (int e = 0; e < E_; e++) { lr[e] = 0.f; lc[e] = 0; }
    for (int t0 = tid; t0 < N_; t0 += 256) {
        int t = b * N_ + t0;
        const float4* rp = (const float4*)(g_raw + (size_t)t * E_);
        float4 r0 = rp[0], r1 = rp[1];
        lr[0] += r0.x; lr[1] += r0.y; lr[2] += r0.z; lr[3] += r0.w;
        lr[4] += r1.x; lr[5] += r1.y; lr[6] += r1.z; lr[7] += r1.w;
        int i1 = g_idx1[t];
#pragma unroll
        for (int e = 0; e < E_; e++) lc[e] += (i1 == e);
    }
#pragma unroll
    for (int e = 0; e < E_; e++) {
        atomicAdd(&ssr[e], lr[e]);
        atomicAdd(&sc1[e], lc[e]);
    }
    __syncthreads();
    if (tid == 0) {
        float s = 0.f;
#pragma unroll
        for (int e = 0; e < E_; e++) s += ssr[e] * (float)sc1[e];
        g_lossp[b] = s;
    }
}

// =================== GEMM machinery (all named scalars, no arrays) ===================
// Stage layout: Ahi 0, Alo 4096, Bhi 8192, Blo 12288  (16 KB/stage, 3 stages)
// A tile [128 m][16 k] bf16, 32B/row = 2 chunks; swizzled chunk' = c ^ ((m>>2)&1)
// B tile [16 k][128 n] bf16, 256B/row = 16 chunks; swizzled chunk' = c ^ (k&7)

#define Z4 make_float4(0.f, 0.f, 0.f, 0.f)
#define DECL_ACC \
    float4 c00=Z4,c01=Z4,c02=Z4,c03=Z4, c10=Z4,c11=Z4,c12=Z4,c13=Z4, \
           c20=Z4,c21=Z4,c22=Z4,c23=Z4, c30=Z4,c31=Z4,c32=Z4,c33=Z4

#define MMA_ADDR_SETUP()                                                    \
    const int lane15 = lane & 15, lhalf = lane >> 4;                        \
    const int m_0 = wm * 64 + 0  + lane15, m_1 = wm * 64 + 16 + lane15;     \
    const int m_2 = wm * 64 + 32 + lane15, m_3 = wm * 64 + 48 + lane15;     \
    const uint32_t la0 = m_0 * 32 + ((lhalf ^ ((m_0 >> 2) & 1)) << 4);      \
    const uint32_t la1 = m_1 * 32 + ((lhalf ^ ((m_1 >> 2) & 1)) << 4);      \
    const uint32_t la2 = m_2 * 32 + ((lhalf ^ ((m_2 >> 2) & 1)) << 4);      \
    const uint32_t la3 = m_3 * 32 + ((lhalf ^ ((m_3 >> 2) & 1)) << 4);      \
    const int nchunk0 = wn * 4;                                             \
    const uint32_t lb0 = lane15 * 256 +                                     \
        (((nchunk0 + 0 + lhalf) ^ (lane15 & 7)) << 4);                      \
    const uint32_t lb1 = lane15 * 256 +                                     \
        (((nchunk0 + 2 + lhalf) ^ (lane15 & 7)) << 4)

// 16 MMAs: A prefix (4 tiles x 4 regs) times B prefix (4 n8-frags x 2 regs)
#define MMA_GRID(AP, BP)                                                    \
    MMA4(c00, AP##00, AP##01, AP##02, AP##03, BP##00, BP##01);              \
    MMA4(c01, AP##00, AP##01, AP##02, AP##03, BP##10, BP##11);              \
    MMA4(c02, AP##00, AP##01, AP##02, AP##03, BP##20, BP##21);              \
    MMA4(c03, AP##00, AP##01, AP##02, AP##03, BP##30, BP##31);              \
    MMA4(c10, AP##10, AP##11, AP##12, AP##13, BP##00, BP##01);              \
    MMA4(c11, AP##10, AP##11, AP##12, AP##13, BP##10, BP##11);              \
    MMA4(c12, AP##10, AP##11, AP##12, AP##13, BP##20, BP##21);              \
    MMA4(c13, AP##10, AP##11, AP##12, AP##13, BP##30, BP##31);              \
    MMA4(c20, AP##20, AP##21, AP##22, AP##23, BP##00, BP##01);              \
    MMA4(c21, AP##20, AP##21, AP##22, AP##23, BP##10, BP##11);              \
    MMA4(c22, AP##20, AP##21, AP##22, AP##23, BP##20, BP##21);              \
    MMA4(c23, AP##20, AP##21, AP##22, AP##23, BP##30, BP##31);              \
    MMA4(c30, AP##30, AP##31, AP##32, AP##33, BP##00, BP##01);              \
    MMA4(c31, AP##30, AP##31, AP##32, AP##33, BP##10, BP##11);              \
    MMA4(c32, AP##30, AP##31, AP##32, AP##33, BP##20, BP##21);              \
    MMA4(c33, AP##30, AP##31, AP##32, AP##33, BP##30, BP##31)

// 3-pass split-bf16 step: hi*hi, hi*lo, lo*hi
#define MMA_STEP(SB) do {                                                   \
    uint32_t h00,h01,h02,h03, h10,h11,h12,h13,                              \
             h20,h21,h22,h23, h30,h31,h32,h33;                              \
    uint32_t b00,b01,b10,b11, b20,b21,b30,b31;                              \
    LDSM4(h00,h01,h02,h03, (SB) + la0);                                     \
    LDSM4(h10,h11,h12,h13, (SB) + la1);                                     \
    LDSM4(h20,h21,h22,h23, (SB) + la2);                                     \
    LDSM4(h30,h31,h32,h33, (SB) + la3);                                     \
    LDSM4T(b00,b01,b10,b11, (SB) + 8192 + lb0);                             \
    LDSM4T(b20,b21,b30,b31, (SB) + 8192 + lb1);                             \
    MMA_GRID(h, b);                                                         \
    {                                                                       \
        uint32_t t00,t01,t10,t11, t20,t21,t30,t31;                          \
        LDSM4T(t00,t01,t10,t11, (SB) + 12288 + lb0);                        \
        LDSM4T(t20,t21,t30,t31, (SB) + 12288 + lb1);                        \
        MMA_GRID(h, t);                                                     \
    }                                                                       \
    {                                                                       \
        uint32_t l00,l01,l02,l03, l10,l11,l12,l13,                          \
                 l20,l21,l22,l23, l30,l31,l32,l33;                          \
        LDSM4(l00,l01,l02,l03, (SB) + 4096 + la0);                          \
        LDSM4(l10,l11,l12,l13, (SB) + 4096 + la1);                          \
        LDSM4(l20,l21,l22,l23, (SB) + 4096 + la2);                          \
        LDSM4(l30,l31,l32,l33, (SB) + 4096 + la3);                          \
        MMA_GRID(l, b);                                                     \
    }                                                                       \
} while (0)

// ---------------- kernel: GEMM1 (gathered x @ w1 -> LeakyReLU -> hid hi/lo) ----------------
__global__ __launch_bounds__(256, 1) void k_gemm1() {
    __shared__ char dsm[NSTAGE * STAGE];
    const uint32_t sb = smem_u32(dsm);
    const int eb = blockIdx.z, e = eb >> 3;
    const int m0 = blockIdx.y * TM, n0 = blockIdx.x * TN;
    const int tid = threadIdx.x;
    const int wid = tid >> 5, lane = tid & 31;
    const int wm = wid >> 2, wn = wid & 3;

    // loader setup
    const int arow = tid >> 1, ac = tid & 1;
    const int tok = g_slot_tok[eb * CAP_ + m0 + arow];
    const int asz = (tok >= 0) ? 16 : 0;
    const size_t xoff = (tok >= 0) ? (size_t)tok * D_ : 0;
    const __nv_bfloat16* axh = g_x_hi + xoff + ac * 8;
    const __nv_bfloat16* axl = g_x_lo + xoff + ac * 8;
    const uint32_t aoff = arow * 32 + ((ac ^ ((arow >> 2) & 1)) << 4);
    const int bkr = tid >> 4, bc = tid & 15;
    const __nv_bfloat16* bwh = g_w1_hi + (size_t)e * D_ * H_ + (size_t)bkr * H_ + n0 + bc * 8;
    const __nv_bfloat16* bwl = g_w1_lo + (size_t)e * D_ * H_ + (size_t)bkr * H_ + n0 + bc * 8;
    const uint32_t boff = bkr * 256 + ((bc ^ (bkr & 7)) << 4);

#define G1_LOAD(st, k0) do {                                          \
        uint32_t sb_ = sb + (uint32_t)(st) * STAGE;                   \
        CP16(sb_ + aoff, axh + (k0), asz);                            \
        CP16(sb_ + 4096 + aoff, axl + (k0), asz);                     \
        CP16(sb_ + 8192 + boff, bwh + (size_t)(k0) * H_, 16);         \
        CP16(sb_ + 12288 + boff, bwl + (size_t)(k0) * H_, 16);        \
    } while (0)

    MMA_ADDR_SETUP();
    DECL_ACC;

    const int CHUNKS = D_ / TKC;  // 32
    G1_LOAD(0, 0);   CP_COMMIT();
    G1_LOAD(1, TKC); CP_COMMIT();
    for (int c = 0; c < CHUNKS; c++) {
        CP_WAIT1();
        __syncthreads();
        if (c + 2 < CHUNKS) { G1_LOAD((c + 2) % NSTAGE, (c + 2) * TKC); CP_COMMIT(); }
        MMA_STEP(sb + (uint32_t)(c % NSTAGE) * STAGE);
    }
#undef G1_LOAD

    // epilogue: LeakyReLU + split -> hid hi/lo
    const int r4 = lane >> 2, c2 = (lane & 3) * 2;
#define G1_EPI(C, I, J) do {                                                \
        int mrow = m0 + wm * 64 + (I) * 16 + r4;                            \
        size_t rb0 = (size_t)(eb * CAP_ + mrow) * H_;                       \
        int n = n0 + wn * 32 + (J) * 8 + c2;                                \
        float v0 = lrelu(C.x), v1 = lrelu(C.y);                             \
        float v2 = lrelu(C.z), v3 = lrelu(C.w);                             \
        __nv_bfloat16 h0, h1, h2, h3, l0, l1, l2, l3;                       \
        splitf(v0, h0, l0); splitf(v1, h1, l1);                             \
        splitf(v2, h2, l2); splitf(v3, h3, l3);                             \
        *(uint32_t*)(g_hid_hi + rb0 + n) = packb2(h0, h1);                  \
        *(uint32_t*)(g_hid_lo + rb0 + n) = packb2(l0, l1);                  \
        *(uint32_t*)(g_hid_hi + rb0 + 8 * H_ + n) = packb2(h2, h3);         \
        *(uint32_t*)(g_hid_lo + rb0 + 8 * H_ + n) = packb2(l2, l3);         \
    } while (0)
    G1_EPI(c00,0,0); G1_EPI(c01,0,1); G1_EPI(c02,0,2); G1_EPI(c03,0,3);
    G1_EPI(c10,1,0); G1_EPI(c11,1,1); G1_EPI(c12,1,2); G1_EPI(c13,1,3);
    G1_EPI(c20,2,0); G1_EPI(c21,2,1); G1_EPI(c22,2,2); G1_EPI(c23,2,3);
    G1_EPI(c30,3,0); G1_EPI(c31,3,1); G1_EPI(c32,3,2); G1_EPI(c33,3,3);
#undef G1_EPI
}

// ---------------- kernel: GEMM2 (hid @ w2 -> eo fp32) ----------------
__global__ __launch_bounds__(256, 1) void k_gemm2() {
    __shared__ char dsm[NSTAGE * STAGE];
    const uint32_t sb = smem_u32(dsm);
    const int eb = blockIdx.z, e = eb >> 3;
    const int m0 = blockIdx.y * TM, n0 = blockIdx.x * TN;
    const int tid = threadIdx.x;
    const int wid = tid >> 5, lane = tid & 31;
    const int wm = wid >> 2, wn = wid & 3;

    const int arow = tid >> 1, ac = tid & 1;
    const __nv_bfloat16* axh = g_hid_hi + (size_t)(eb * CAP_ + m0 + arow) * H_ + ac * 8;
    const __nv_bfloat16* axl = g_hid_lo + (size_t)(eb * CAP_ + m0 + arow) * H_ + ac * 8;
    const uint32_t aoff = arow * 32 + ((ac ^ ((arow >> 2) & 1)) << 4);
    const int bkr = tid >> 4, bc = tid & 15;
    const __nv_bfloat16* bwh = g_w2_hi + (size_t)e * H_ * D_ + (size_t)bkr * D_ + n0 + bc * 8;
    const __nv_bfloat16* bwl = g_w2_lo + (size_t)e * H_ * D_ + (size_t)bkr * D_ + n0 + bc * 8;
    const uint32_t boff = bkr * 256 + ((bc ^ (bkr & 7)) << 4);

#define G2_LOAD(st, k0) do {                                          \
        uint32_t sb_ = sb + (uint32_t)(st) * STAGE;                   \
        CP16(sb_ + aoff, axh + (k0), 16);                             \
        CP16(sb_ + 4096 + aoff, axl + (k0), 16);                      \
        CP16(sb_ + 8192 + boff, bwh + (size_t)(k0) * D_, 16);         \
        CP16(sb_ + 12288 + boff, bwl + (size_t)(k0) * D_, 16);        \
    } while (0)

    MMA_ADDR_SETUP();
    DECL_ACC;

    const int CHUNKS = H_ / TKC;  // 64
    G2_LOAD(0, 0);   CP_COMMIT();
    G2_LOAD(1, TKC); CP_COMMIT();
    for (int c = 0; c < CHUNKS; c++) {
        CP_WAIT1();
        __syncthreads();
        if (c + 2 < CHUNKS) { G2_LOAD((c + 2) % NSTAGE, (c + 2) * TKC); CP_COMMIT(); }
        MMA_STEP(sb + (uint32_t)(c % NSTAGE) * STAGE);
    }
#undef G2_LOAD

    // epilogue: store eo fp32
    const int r4 = lane >> 2, c2 = (lane & 3) * 2;
#define G2_EPI(C, I, J) do {                                                \
        int mrow = m0 + wm * 64 + (I) * 16 + r4;                            \
        size_t rb0 = (size_t)(eb * CAP_ + mrow) * D_;                       \
        int n = n0 + wn * 32 + (J) * 8 + c2;                                \
        *(float2*)(g_eo + rb0 + n) = make_float2(C.x, C.y);                 \
        *(float2*)(g_eo + rb0 + 8 * D_ + n) = make_float2(C.z, C.w);        \
    } while (0)
    G2_EPI(c00,0,0); G2_EPI(c01,0,1); G2_EPI(c02,0,2); G2_EPI(c03,0,3);
    G2_EPI(c10,1,0); G2_EPI(c11,1,1); G2_EPI(c12,1,2); G2_EPI(c13,1,3);
    G2_EPI(c20,2,0); G2_EPI(c21,2,1); G2_EPI(c22,2,2); G2_EPI(c23,2,3);
    G2_EPI(c30,3,0); G2_EPI(c31,3,1); G2_EPI(c32,3,2); G2_EPI(c33,3,3);
#undef G2_EPI
}

// ---------------- kernel: combine (warp per token) ----------------
__global__ void k_combine(float* __restrict__ out) {
    int w = (blockIdx.x * blockDim.x + threadIdx.x) >> 5;
    int lane = threadIdx.x & 31;
    if (w >= BN_) return;
    int s1 = g_tslot1[w], s2 = g_tslot2[w];
    float g1 = g_g1[w], g2 = g_g2[w];
    const float4* e1p = (s1 >= 0) ? (const float4*)(g_eo + (size_t)s1 * D_) : nullptr;
    const float4* e2p = (s2 >= 0) ? (const float4*)(g_eo + (size_t)s2 * D_) : nullptr;
    float4* o = (float4*)(out + (size_t)w * D_);
#pragma unroll
    for (int i = lane; i < D_ / 4; i += 32) {
        float4 a = make_float4(0.f, 0.f, 0.f, 0.f);
        if (e1p) {
            float4 t = e1p[i];
            a.x = g1 * t.x; a.y = g1 * t.y; a.z = g1 * t.z; a.w = g1 * t.w;
        }
        if (e2p) {
            float4 t = e2p[i];
            a.x += g2 * t.x; a.y += g2 * t.y; a.z += g2 * t.z; a.w += g2 * t.w;
        }
        o[i] = a;
    }
}

// ---------------- kernel: loss ----------------
__global__ void k_loss(float* __restrict__ out, int out_n) {
    if ((size_t)out_n > OUT_MAIN_) {
        float s = 0.f;
#pragma unroll
        for (int b = 0; b < B_; b++) s += g_lossp[b];
        out[OUT_MAIN_] = 0.01f * s / ((float)N_ * (float)N_);
    }
}

// ---------------- entry ----------------
extern "C" void kernel_launch(void* const* d_in, const int* in_sizes, int n_in,
                              void* d_out, int out_size) {
    const float* x     = (const float*)d_in[0];
    const float* probs = (const float*)d_in[1];
    const float* wg    = (const float*)d_in[2];
    const float* w1    = (const float*)d_in[3];
    const float* w2    = (const float*)d_in[4];
    float* out = (float*)d_out;

    k_init<<<(SLOTS_ + 255) / 256, 256>>>();
    k_gate<<<BN_ / 4, 128>>>(x, probs, wg);
    k_scan<<<B_, 32>>>();
    k_lsum<<<B_, 256>>>();
    k_split_x <<<(BN_ * D_ / 4 + 255) / 256, 256>>>(x);
    k_split_w1<<<(E_ * D_ * H_ / 4 + 255) / 256, 256>>>(w1);
    k_split_w2<<<(E_ * H_ * D_ / 4 + 255) / 256, 256>>>(w2);
    k_gemm1<<<dim3(H_ / TN, CAP_ / TM, EB_), 256>>>();
    k_gemm2<<<dim3(D_ / TN, CAP_ / TM, EB_), 256>>>();
    k_combine<<<(BN_ * 32) / 256, 256>>>(out);
    k_loss<<<1, 1>>>(out, out_size);
}

// round 9
// speedup vs baseline: 1.7361x; 1.0377x over previous
#include <cuda_runtime.h>
#include <cuda_bf16.h>
#include <cstdint>
#include <math.h>

// ---------------- problem constants ----------------
#define B_    8
#define N_    2048
#define D_    512
#define H_    1024
#define E_    8
#define CAP_  512
#define BN_   (B_*N_)
#define EB_   (E_*B_)
#define SLOTS_ (EB_*CAP_)
#define OUT_MAIN_ ((size_t)B_*N_*D_)

// GEMM tiling: CTA 128x128, k-chunk 16, 3-stage cp.async pipeline
#define TM 128
#define TN 128
#define TKC 16
#define STAGE 16384            // Ahi 4K + Alo 4K + Bhi 4K + Blo 4K
#define NSTAGE 3               // 48 KB static shared

#define LSEG 8                 // lsum segments per batch
#define LBLK (B_*LSEG)         // 64 lsum blocks

// ---------------- scratch ----------------
__device__ float g_raw[BN_*E_];
__device__ int   g_idx1[BN_];
__device__ int   g_idx2[BN_];
__device__ float g_g1[BN_];
__device__ float g_g2[BN_];
__device__ int   g_keep2[BN_];
__device__ int   g_slot_tok[SLOTS_];
__device__ int   g_tslot1[BN_];
__device__ int   g_tslot2[BN_];
__device__ float g_srp[LBLK][E_];   // per-segment raw-prob sums
__device__ int   g_c1p[LBLK][E_];   // per-segment first-choice counts
__device__ __align__(16) __nv_bfloat16 g_x_hi[(size_t)BN_*D_];
__device__ __align__(16) __nv_bfloat16 g_x_lo[(size_t)BN_*D_];
__device__ __align__(16) __nv_bfloat16 g_w1_hi[(size_t)E_*D_*H_];
__device__ __align__(16) __nv_bfloat16 g_w1_lo[(size_t)E_*D_*H_];
__device__ __align__(16) __nv_bfloat16 g_w2_hi[(size_t)E_*H_*D_];
__device__ __align__(16) __nv_bfloat16 g_w2_lo[(size_t)E_*H_*D_];
__device__ __align__(16) __nv_bfloat16 g_hid_hi[(size_t)EB_*CAP_*H_];
__device__ __align__(16) __nv_bfloat16 g_hid_lo[(size_t)EB_*CAP_*H_];
__device__ __align__(16) float         g_eo[(size_t)EB_*CAP_*D_];

// ---------------- PTX helpers (compute_100-safe; no pointer params) ----------------
__device__ __forceinline__ uint32_t smem_u32(const void* p) {
    uint32_t a;
    asm("{ .reg .u64 t; cvta.to.shared.u64 t, %1; cvt.u32.u64 %0, t; }"
        : "=r"(a) : "l"(p));
    return a;
}
#define CP16(dst, src, sz) \
    asm volatile("cp.async.cg.shared.global [%0], [%1], 16, %2;" \
                 :: "r"(dst), "l"(src), "r"(sz) : "memory")
#define CP_COMMIT() asm volatile("cp.async.commit_group;" ::: "memory")
#define CP_WAIT1()  asm volatile("cp.async.wait_group 1;" ::: "memory")

#define LDSM4(R0, R1, R2, R3, ADDR) \
    asm volatile("ldmatrix.sync.aligned.m8n8.x4.shared.b16 {%0,%1,%2,%3}, [%4];" \
        : "=r"(R0), "=r"(R1), "=r"(R2), "=r"(R3) : "r"(ADDR))
#define LDSM4T(R0, R1, R2, R3, ADDR) \
    asm volatile("ldmatrix.sync.aligned.m8n8.x4.trans.shared.b16 {%0,%1,%2,%3}, [%4];" \
        : "=r"(R0), "=r"(R1), "=r"(R2), "=r"(R3) : "r"(ADDR))
#define MMA4(C, A0, A1, A2, A3, B0, B1) \
    asm volatile("mma.sync.aligned.m16n8k16.row.col.f32.bf16.bf16.f32 " \
        "{%0,%1,%2,%3}, {%4,%5,%6,%7}, {%8,%9}, {%0,%1,%2,%3};" \
        : "+f"(C.x), "+f"(C.y), "+f"(C.z), "+f"(C.w) \
        : "r"(A0), "r"(A1), "r"(A2), "r"(A3), "r"(B0), "r"(B1))

__device__ __forceinline__ float lrelu(float v) { return v >= 0.f ? v : 0.01f * v; }
__device__ __forceinline__ void splitf(float v, __nv_bfloat16& h, __nv_bfloat16& l) {
    h = __float2bfloat16(v);
    l = __float2bfloat16(v - __bfloat162float(h));
}
__device__ __forceinline__ uint32_t packb2(__nv_bfloat16 a, __nv_bfloat16 b) {
    return (uint32_t)__bfloat16_as_ushort(a) | ((uint32_t)__bfloat16_as_ushort(b) << 16);
}
__device__ __forceinline__ void split4(float4 v, uint2& uh, uint2& ul) {
    __nv_bfloat16 h0, h1, h2, h3, l0, l1, l2, l3;
    splitf(v.x, h0, l0); splitf(v.y, h1, l1);
    splitf(v.z, h2, l2); splitf(v.w, h3, l3);
    uh = make_uint2(packb2(h0, h1), packb2(h2, h3));
    ul = make_uint2(packb2(l0, l1), packb2(l2, l3));
}

// ---------------- split kernels (reference __device__ globals directly) ----------------
__global__ void k_split_x(const float* __restrict__ src) {
    int i = blockIdx.x * blockDim.x + threadIdx.x;
    if (i >= BN_ * D_ / 4) return;
    uint2 uh, ul;
    split4(((const float4*)src)[i], uh, ul);
    ((uint2*)g_x_hi)[i] = uh;
    ((uint2*)g_x_lo)[i] = ul;
}
__global__ void k_split_w1(const float* __restrict__ src) {
    int i = blockIdx.x * blockDim.x + threadIdx.x;
    if (i >= E_ * D_ * H_ / 4) return;
    uint2 uh, ul;
    split4(((const float4*)src)[i], uh, ul);
    ((uint2*)g_w1_hi)[i] = uh;
    ((uint2*)g_w1_lo)[i] = ul;
}
__global__ void k_split_w2(const float* __restrict__ src) {
    int i = blockIdx.x * blockDim.x + threadIdx.x;
    if (i >= E_ * H_ * D_ / 4) return;
    uint2 uh, ul;
    split4(((const float4*)src)[i], uh, ul);
    ((uint2*)g_w2_hi)[i] = uh;
    ((uint2*)g_w2_lo)[i] = ul;
}

// ---------------- kernel: gating (warp per token) ----------------
__global__ void k_gate(const float* __restrict__ x,
                       const float* __restrict__ probs,
                       const float* __restrict__ wg) {
    int lane = threadIdx.x & 31;
    int t = blockIdx.x * (blockDim.x >> 5) + (threadIdx.x >> 5);
    if (t >= BN_) return;
    const float* xr = x + (size_t)t * D_;
    float acc[E_];
#pragma unroll
    for (int e = 0; e < E_; e++) acc[e] = 0.f;
    for (int k = lane; k < D_; k += 32) {
        float xv = xr[k];
        const float4* wr = (const float4*)(wg + k * E_);
        float4 w0 = wr[0], w1v = wr[1];
        acc[0] = fmaf(xv, w0.x, acc[0]);  acc[1] = fmaf(xv, w0.y, acc[1]);
        acc[2] = fmaf(xv, w0.z, acc[2]);  acc[3] = fmaf(xv, w0.w, acc[3]);
        acc[4] = fmaf(xv, w1v.x, acc[4]); acc[5] = fmaf(xv, w1v.y, acc[5]);
        acc[6] = fmaf(xv, w1v.z, acc[6]); acc[7] = fmaf(xv, w1v.w, acc[7]);
    }
#pragma unroll
    for (int off = 16; off; off >>= 1)
#pragma unroll
        for (int e = 0; e < E_; e++)
            acc[e] += __shfl_xor_sync(0xffffffffu, acc[e], off);
    if (lane == 0) {
        float m = acc[0];
#pragma unroll
        for (int e = 1; e < E_; e++) m = fmaxf(m, acc[e]);
        float r[E_], s = 0.f;
#pragma unroll
        for (int e = 0; e < E_; e++) { r[e] = expf(acc[e] - m); s += r[e]; }
        float inv = 1.f / s;
#pragma unroll
        for (int e = 0; e < E_; e++) r[e] *= inv;
        int i1 = 0; float g1 = r[0];
#pragma unroll
        for (int e = 1; e < E_; e++) if (r[e] > g1) { g1 = r[e]; i1 = e; }
        int i2 = -1; float g2 = -1.f;
#pragma unroll
        for (int e = 0; e < E_; e++) if (e != i1 && r[e] > g2) { g2 = r[e]; i2 = e; }
        float denom = g1 + g2 + 1e-9f;
        float g1n = g1 / denom, g2n = g2 / denom;
        g_idx1[t] = i1; g_idx2[t] = i2;
        g_g1[t] = g1n;  g_g2[t] = g2n;
        g_keep2[t] = probs[t] < (g2n / 0.2f);
        float4* rr = (float4*)(g_raw + (size_t)t * E_);
        rr[0] = make_float4(r[0], r[1], r[2], r[3]);
        rr[1] = make_float4(r[4], r[5], r[6], r[7]);
    }
}

// ---------------- kernel: route = capacity scan (blocks 0..7) + lsum (blocks 8..71) ----------------
__global__ void k_route() {
    if (blockIdx.x < B_) {
        // ---- capacity scan: one warp per batch; tail-fills slot_tok with -1 ----
        if (threadIdx.x >= 32) return;
        int b = blockIdx.x;
        int lane = threadIdx.x;
        __shared__ int cnt[E_], m1c[E_];
        if (lane < E_) cnt[lane] = 0;
        __syncwarp();
        unsigned lmask = (1u << lane) - 1u;

        int e1 = g_idx1[b * N_ + lane];
        for (int base = 0; base < N_; base += 32) {
            int e1n = 0;
            if (base + 32 < N_) e1n = g_idx1[b * N_ + base + 32 + lane];
            int tcur = b * N_ + base + lane;
            unsigned mm = __match_any_sync(0xffffffffu, e1);
            int rank = __popc(mm & lmask);
            int bc = cnt[e1];
            __syncwarp();
            int pos = bc + rank;
            int slot = -1;
            if (pos < CAP_) {
                slot = (e1 * B_ + b) * CAP_ + pos;
                g_slot_tok[slot] = tcur;
            }
            g_tslot1[tcur] = slot;
            if (rank == 0) cnt[e1] = bc + __popc(mm);
            __syncwarp();
            e1 = e1n;
        }
        if (lane < E_) { m1c[lane] = min(cnt[lane], CAP_); cnt[lane] = 0; }
        __syncwarp();

        int alive = g_keep2[b * N_ + lane];
        int e2 = g_idx2[b * N_ + lane];
        for (int base = 0; base < N_; base += 32) {
            int alin = 0, e2n = 0;
            if (base + 32 < N_) {
                int tn = b * N_ + base + 32 + lane;
                alin = g_keep2[tn]; e2n = g_idx2[tn];
            }
            int tcur = b * N_ + base + lane;
            int key = alive ? e2 : (E_ + lane);
            unsigned mm = __match_any_sync(0xffffffffu, key);
            int rank = __popc(mm & lmask);
            int bc = cnt[e2];
            int m1 = m1c[e2];
            __syncwarp();
            int slot = -1;
            if (alive) {
                int pos = m1 + bc + rank;
                if (pos < CAP_) {
                    slot = (e2 * B_ + b) * CAP_ + pos;
                    g_slot_tok[slot] = tcur;
                }
                if (rank == 0) cnt[e2] = bc + __popc(mm);
            }
            g_tslot2[tcur] = slot;
            __syncwarp();
            alive = alin; e2 = e2n;
        }
        // tail-fill empty slots (replaces k_init): filled region is contiguous [0, fill)
        __syncwarp();
#pragma unroll
        for (int e = 0; e < E_; e++) {
            int fill = min(m1c[e] + cnt[e], CAP_);
            int sbase = (e * B_ + b) * CAP_;
            for (int i = fill + lane; i < CAP_; i += 32)
                g_slot_tok[sbase + i] = -1;
        }
    } else {
        // ---- lsum partials: 256 tokens per block ----
        int q = blockIdx.x - B_;           // 0..63
        int b = q >> 3, seg = q & 7;
        int tid = threadIdx.x;
        __shared__ float ssr[E_];
        __shared__ int   sc1[E_];
        if (tid < E_) { ssr[tid] = 0.f; sc1[tid] = 0; }
        __syncthreads();
        int t = b * N_ + seg * 256 + tid;
        const float4* rp = (const float4*)(g_raw + (size_t)t * E_);
        float4 r0 = rp[0], r1 = rp[1];
        int i1 = g_idx1[t];
        float lr0 = r0.x, lr1 = r0.y, lr2 = r0.z, lr3 = r0.w;
        float lr4 = r1.x, lr5 = r1.y, lr6 = r1.z, lr7 = r1.w;
#pragma unroll
        for (int off = 16; off; off >>= 1) {
            lr0 += __shfl_xor_sync(0xffffffffu, lr0, off);
            lr1 += __shfl_xor_sync(0xffffffffu, lr1, off);
            lr2 += __shfl_xor_sync(0xffffffffu, lr2, off);
            lr3 += __shfl_xor_sync(0xffffffffu, lr3, off);
            lr4 += __shfl_xor_sync(0xffffffffu, lr4, off);
            lr5 += __shfl_xor_sync(0xffffffffu, lr5, off);
            lr6 += __shfl_xor_sync(0xffffffffu, lr6, off);
            lr7 += __shfl_xor_sync(0xffffffffu, lr7, off);
        }
        if ((tid & 31) == 0) {
            atomicAdd(&ssr[0], lr0); atomicAdd(&ssr[1], lr1);
            atomicAdd(&ssr[2], lr2); atomicAdd(&ssr[3], lr3);
            atomicAdd(&ssr[4], lr4); atomicAdd(&ssr[5], lr5);
            atomicAdd(&ssr[6], lr6); atomicAdd(&ssr[7], lr7);
        }
        atomicAdd(&sc1[i1], 1);
        __syncthreads();
        if (tid < E_) {
            g_srp[q][tid] = ssr[tid];
            g_c1p[q][tid] = sc1[tid];
        }
    }
}

// =================== GEMM machinery (unchanged from R8 — passing) ===================
// Stage layout: Ahi 0, Alo 4096, Bhi 8192, Blo 12288  (16 KB/stage, 3 stages)
// A tile [128 m][16 k] bf16, 32B/row = 2 chunks; swizzled chunk' = c ^ ((m>>2)&1)
// B tile [16 k][128 n] bf16, 256B/row = 16 chunks; swizzled chunk' = c ^ (k&7)

#define Z4 make_float4(0.f, 0.f, 0.f, 0.f)
#define DECL_ACC \
    float4 c00=Z4,c01=Z4,c02=Z4,c03=Z4, c10=Z4,c11=Z4,c12=Z4,c13=Z4, \
           c20=Z4,c21=Z4,c22=Z4,c23=Z4, c30=Z4,c31=Z4,c32=Z4,c33=Z4

#define MMA_ADDR_SETUP()                                                    \
    const int lane15 = lane & 15, lhalf = lane >> 4;                        \
    const int m_0 = wm * 64 + 0  + lane15, m_1 = wm * 64 + 16 + lane15;     \
    const int m_2 = wm * 64 + 32 + lane15, m_3 = wm * 64 + 48 + lane15;     \
    const uint32_t la0 = m_0 * 32 + ((lhalf ^ ((m_0 >> 2) & 1)) << 4);      \
    const uint32_t la1 = m_1 * 32 + ((lhalf ^ ((m_1 >> 2) & 1)) << 4);      \
    const uint32_t la2 = m_2 * 32 + ((lhalf ^ ((m_2 >> 2) & 1)) << 4);      \
    const uint32_t la3 = m_3 * 32 + ((lhalf ^ ((m_3 >> 2) & 1)) << 4);      \
    const int nchunk0 = wn * 4;                                             \
    const uint32_t lb0 = lane15 * 256 +                                     \
        (((nchunk0 + 0 + lhalf) ^ (lane15 & 7)) << 4);                      \
    const uint32_t lb1 = lane15 * 256 +                                     \
        (((nchunk0 + 2 + lhalf) ^ (lane15 & 7)) << 4)

#define MMA_GRID(AP, BP)                                                    \
    MMA4(c00, AP##00, AP##01, AP##02, AP##03, BP##00, BP##01);              \
    MMA4(c01, AP##00, AP##01, AP##02, AP##03, BP##10, BP##11);              \
    MMA4(c02, AP##00, AP##01, AP##02, AP##03, BP##20, BP##21);              \
    MMA4(c03, AP##00, AP##01, AP##02, AP##03, BP##30, BP##31);              \
    MMA4(c10, AP##10, AP##11, AP##12, AP##13, BP##00, BP##01);              \
    MMA4(c11, AP##10, AP##11, AP##12, AP##13, BP##10, BP##11);              \
    MMA4(c12, AP##10, AP##11, AP##12, AP##13, BP##20, BP##21);              \
    MMA4(c13, AP##10, AP##11, AP##12, AP##13, BP##30, BP##31);              \
    MMA4(c20, AP##20, AP##21, AP##22, AP##23, BP##00, BP##01);              \
    MMA4(c21, AP##20, AP##21, AP##22, AP##23, BP##10, BP##11);              \
    MMA4(c22, AP##20, AP##21, AP##22, AP##23, BP##20, BP##21);              \
    MMA4(c23, AP##20, AP##21, AP##22, AP##23, BP##30, BP##31);              \
    MMA4(c30, AP##30, AP##31, AP##32, AP##33, BP##00, BP##01);              \
    MMA4(c31, AP##30, AP##31, AP##32, AP##33, BP##10, BP##11);              \
    MMA4(c32, AP##30, AP##31, AP##32, AP##33, BP##20, BP##21);              \
    MMA4(c33, AP##30, AP##31, AP##32, AP##33, BP##30, BP##31)

#define MMA_STEP(SB) do {                                                   \
    uint32_t h00,h01,h02,h03, h10,h11,h12,h13,                              \
             h20,h21,h22,h23, h30,h31,h32,h33;                              \
    uint32_t b00,b01,b10,b11, b20,b21,b30,b31;                              \
    LDSM4(h00,h01,h02,h03, (SB) + la0);                                     \
    LDSM4(h10,h11,h12,h13, (SB) + la1);                                     \
    LDSM4(h20,h21,h22,h23, (SB) + la2);                                     \
    LDSM4(h30,h31,h32,h33, (SB) + la3);                                     \
    LDSM4T(b00,b01,b10,b11, (SB) + 8192 + lb0);                             \
    LDSM4T(b20,b21,b30,b31, (SB) + 8192 + lb1);                             \
    MMA_GRID(h, b);                                                         \
    {                                                                       \
        uint32_t t00,t01,t10,t11, t20,t21,t30,t31;                          \
        LDSM4T(t00,t01,t10,t11, (SB) + 12288 + lb0);                        \
        LDSM4T(t20,t21,t30,t31, (SB) + 12288 + lb1);                        \
        MMA_GRID(h, t);                                                     \
    }                                                                       \
    {                                                                       \
        uint32_t l00,l01,l02,l03, l10,l11,l12,l13,                          \
                 l20,l21,l22,l23, l30,l31,l32,l33;                          \
        LDSM4(l00,l01,l02,l03, (SB) + 4096 + la0);                          \
        LDSM4(l10,l11,l12,l13, (SB) + 4096 + la1);                          \
        LDSM4(l20,l21,l22,l23, (SB) + 4096 + la2);                          \
        LDSM4(l30,l31,l32,l33, (SB) + 4096 + la3);                          \
        MMA_GRID(l, b);                                                     \
    }                                                                       \
} while (0)

// ---------------- kernel: GEMM1 (gathered x @ w1 -> LeakyReLU -> hid hi/lo) ----------------
__global__ __launch_bounds__(256, 1) void k_gemm1() {
    __shared__ char dsm[NSTAGE * STAGE];
    const uint32_t sb = smem_u32(dsm);
    const int eb = blockIdx.z, e = eb >> 3;
    const int m0 = blockIdx.y * TM, n0 = blockIdx.x * TN;
    const int tid = threadIdx.x;
    const int wid = tid >> 5, lane = tid & 31;
    const int wm = wid >> 2, wn = wid & 3;

    const int arow = tid >> 1, ac = tid & 1;
    const int tok = g_slot_tok[eb * CAP_ + m0 + arow];
    const int asz = (tok >= 0) ? 16 : 0;
    const size_t xoff = (tok >= 0) ? (size_t)tok * D_ : 0;
    const __nv_bfloat16* axh = g_x_hi + xoff + ac * 8;
    const __nv_bfloat16* axl = g_x_lo + xoff + ac * 8;
    const uint32_t aoff = arow * 32 + ((ac ^ ((arow >> 2) & 1)) << 4);
    const int bkr = tid >> 4, bc = tid & 15;
    const __nv_bfloat16* bwh = g_w1_hi + (size_t)e * D_ * H_ + (size_t)bkr * H_ + n0 + bc * 8;
    const __nv_bfloat16* bwl = g_w1_lo + (size_t)e * D_ * H_ + (size_t)bkr * H_ + n0 + bc * 8;
    const uint32_t boff = bkr * 256 + ((bc ^ (bkr & 7)) << 4);

#define G1_LOAD(st, k0) do {                                          \
        uint32_t sb_ = sb + (uint32_t)(st) * STAGE;                   \
        CP16(sb_ + aoff, axh + (k0), asz);                            \
        CP16(sb_ + 4096 + aoff, axl + (k0), asz);                     \
        CP16(sb_ + 8192 + boff, bwh + (size_t)(k0) * H_, 16);         \
        CP16(sb_ + 12288 + boff, bwl + (size_t)(k0) * H_, 16);        \
    } while (0)

    MMA_ADDR_SETUP();
    DECL_ACC;

    const int CHUNKS = D_ / TKC;  // 32
    G1_LOAD(0, 0);   CP_COMMIT();
    G1_LOAD(1, TKC); CP_COMMIT();
    for (int c = 0; c < CHUNKS; c++) {
        CP_WAIT1();
        __syncthreads();
        if (c + 2 < CHUNKS) { G1_LOAD((c + 2) % NSTAGE, (c + 2) * TKC); CP_COMMIT(); }
        MMA_STEP(sb + (uint32_t)(c % NSTAGE) * STAGE);
    }
#undef G1_LOAD

    const int r4 = lane >> 2, c2 = (lane & 3) * 2;
#define G1_EPI(C, I, J) do {                                                \
        int mrow = m0 + wm * 64 + (I) * 16 + r4;                            \
        size_t rb0 = (size_t)(eb * CAP_ + mrow) * H_;                       \
        int n = n0 + wn * 32 + (J) * 8 + c2;                                \
        float v0 = lrelu(C.x), v1 = lrelu(C.y);                             \
        float v2 = lrelu(C.z), v3 = lrelu(C.w);                             \
        __nv_bfloat16 h0, h1, h2, h3, l0, l1, l2, l3;                       \
        splitf(v0, h0, l0); splitf(v1, h1, l1);                             \
        splitf(v2, h2, l2); splitf(v3, h3, l3);                             \
        *(uint32_t*)(g_hid_hi + rb0 + n) = packb2(h0, h1);                  \
        *(uint32_t*)(g_hid_lo + rb0 + n) = packb2(l0, l1);                  \
        *(uint32_t*)(g_hid_hi + rb0 + 8 * H_ + n) = packb2(h2, h3);         \
        *(uint32_t*)(g_hid_lo + rb0 + 8 * H_ + n) = packb2(l2, l3);         \
    } while (0)
    G1_EPI(c00,0,0); G1_EPI(c01,0,1); G1_EPI(c02,0,2); G1_EPI(c03,0,3);
    G1_EPI(c10,1,0); G1_EPI(c11,1,1); G1_EPI(c12,1,2); G1_EPI(c13,1,3);
    G1_EPI(c20,2,0); G1_EPI(c21,2,1); G1_EPI(c22,2,2); G1_EPI(c23,2,3);
    G1_EPI(c30,3,0); G1_EPI(c31,3,1); G1_EPI(c32,3,2); G1_EPI(c33,3,3);
#undef G1_EPI
}

// ---------------- kernel: GEMM2 (hid @ w2 -> eo fp32) ----------------
__global__ __launch_bounds__(256, 1) void k_gemm2() {
    __shared__ char dsm[NSTAGE * STAGE];
    const uint32_t sb = smem_u32(dsm);
    const int eb = blockIdx.z, e = eb >> 3;
    const int m0 = blockIdx.y * TM, n0 = blockIdx.x * TN;
    const int tid = threadIdx.x;
    const int wid = tid >> 5, lane = tid & 31;
    const int wm = wid >> 2, wn = wid & 3;

    const int arow = tid >> 1, ac = tid & 1;
    const __nv_bfloat16* axh = g_hid_hi + (size_t)(eb * CAP_ + m0 + arow) * H_ + ac * 8;
    const __nv_bfloat16* axl = g_hid_lo + (size_t)(eb * CAP_ + m0 + arow) * H_ + ac * 8;
    const uint32_t aoff = arow * 32 + ((ac ^ ((arow >> 2) & 1)) << 4);
    const int bkr = tid >> 4, bc = tid & 15;
    const __nv_bfloat16* bwh = g_w2_hi + (size_t)e * H_ * D_ + (size_t)bkr * D_ + n0 + bc * 8;
    const __nv_bfloat16* bwl = g_w2_lo + (size_t)e * H_ * D_ + (size_t)bkr * D_ + n0 + bc * 8;
    const uint32_t boff = bkr * 256 + ((bc ^ (bkr & 7)) << 4);

#define G2_LOAD(st, k0) do {                                          \
        uint32_t sb_ = sb + (uint32_t)(st) * STAGE;                   \
        CP16(sb_ + aoff, axh + (k0), 16);                             \
        CP16(sb_ + 4096 + aoff, axl + (k0), 16);                      \
        CP16(sb_ + 8192 + boff, bwh + (size_t)(k0) * D_, 16);         \
        CP16(sb_ + 12288 + boff, bwl + (size_t)(k0) * D_, 16);        \
    } while (0)

    MMA_ADDR_SETUP();
    DECL_ACC;

    const int CHUNKS = H_ / TKC;  // 64
    G2_LOAD(0, 0);   CP_COMMIT();
    G2_LOAD(1, TKC); CP_COMMIT();
    for (int c = 0; c < CHUNKS; c++) {
        CP_WAIT1();
        __syncthreads();
        if (c + 2 < CHUNKS) { G2_LOAD((c + 2) % NSTAGE, (c + 2) * TKC); CP_COMMIT(); }
        MMA_STEP(sb + (uint32_t)(c % NSTAGE) * STAGE);
    }
#undef G2_LOAD

    const int r4 = lane >> 2, c2 = (lane & 3) * 2;
#define G2_EPI(C, I, J) do {                                                \
        int mrow = m0 + wm * 64 + (I) * 16 + r4;                            \
        size_t rb0 = (size_t)(eb * CAP_ + mrow) * D_;                       \
        int n = n0 + wn * 32 + (J) * 8 + c2;                                \
        *(float2*)(g_eo + rb0 + n) = make_float2(C.x, C.y);                 \
        *(float2*)(g_eo + rb0 + 8 * D_ + n) = make_float2(C.z, C.w);        \
    } while (0)
    G2_EPI(c00,0,0); G2_EPI(c01,0,1); G2_EPI(c02,0,2); G2_EPI(c03,0,3);
    G2_EPI(c10,1,0); G2_EPI(c11,1,1); G2_EPI(c12,1,2); G2_EPI(c13,1,3);
    G2_EPI(c20,2,0); G2_EPI(c21,2,1); G2_EPI(c22,2,2); G2_EPI(c23,2,3);
    G2_EPI(c30,3,0); G2_EPI(c31,3,1); G2_EPI(c32,3,2); G2_EPI(c33,3,3);
#undef G2_EPI
}

// ---------------- kernel: combine (warp per token) + loss reduction ----------------
__global__ void k_combine(float* __restrict__ out, int out_n) {
    // loss: deterministic serial reduction of per-segment partials
    if (blockIdx.x == 0 && threadIdx.x == 0 && (size_t)out_n > OUT_MAIN_) {
        float total = 0.f;
#pragma unroll
        for (int b = 0; b < B_; b++) {
            float lb = 0.f;
#pragma unroll
            for (int e = 0; e < E_; e++) {
                float sr = 0.f; int c1 = 0;
#pragma unroll
                for (int seg = 0; seg < LSEG; seg++) {
                    sr += g_srp[b * LSEG + seg][e];
                    c1 += g_c1p[b * LSEG + seg][e];
                }
                lb += sr * (float)c1;
            }
            total += lb;
        }
        out[OUT_MAIN_] = 0.01f * total / ((float)N_ * (float)N_);
    }

    int w = (blockIdx.x * blockDim.x + threadIdx.x) >> 5;
    int lane = threadIdx.x & 31;
    if (w >= BN_) return;
    int s1 = g_tslot1[w], s2 = g_tslot2[w];
    float g1 = g_g1[w], g2 = g_g2[w];
    const float4* e1p = (s1 >= 0) ? (const float4*)(g_eo + (size_t)s1 * D_) : nullptr;
    const float4* e2p = (s2 >= 0) ? (const float4*)(g_eo + (size_t)s2 * D_) : nullptr;
    float4* o = (float4*)(out + (size_t)w * D_);
#pragma unroll
    for (int i = lane; i < D_ / 4; i += 32) {
        float4 a = make_float4(0.f, 0.f, 0.f, 0.f);
        if (e1p) {
            float4 t = e1p[i];
            a.x = g1 * t.x; a.y = g1 * t.y; a.z = g1 * t.z; a.w = g1 * t.w;
        }
        if (e2p) {
            float4 t = e2p[i];
            a.x += g2 * t.x; a.y += g2 * t.y; a.z += g2 * t.z; a.w += g2 * t.w;
        }
        o[i] = a;
    }
}

// ---------------- entry ----------------
// Launch order puts k_gemm1 at the 6th launch so ncu (-s 5 -c 1) profiles it.
extern "C" void kernel_launch(void* const* d_in, const int* in_sizes, int n_in,
                              void* d_out, int out_size) {
    const float* x     = (const float*)d_in[0];
    const float* probs = (const float*)d_in[1];
    const float* wg    = (const float*)d_in[2];
    const float* w1    = (const float*)d_in[3];
    const float* w2    = (const float*)d_in[4];
    float* out = (float*)d_out;

    k_gate<<<BN_ / 4, 128>>>(x, probs, wg);                          // 1
    k_split_x <<<(BN_ * D_ / 4 + 255) / 256, 256>>>(x);              // 2
    k_split_w1<<<(E_ * D_ * H_ / 4 + 255) / 256, 256>>>(w1);         // 3
    k_split_w2<<<(E_ * H_ * D_ / 4 + 255) / 256, 256>>>(w2);         // 4
    k_route<<<B_ + LBLK, 256>>>();                                   // 5
    k_gemm1<<<dim3(H_ / TN, CAP_ / TM, EB_), 256>>>();               // 6 <- ncu
    k_gemm2<<<dim3(D_ / TN, CAP_ / TM, EB_), 256>>>();               // 7
    k_combine<<<(BN_ * 32) / 256, 256>>>(out, out_size);             // 8
}